// round 17
// baseline (speedup 1.0000x reference)
#include <cuda_runtime.h>
#include <cuda_bf16.h>
#include <math.h>

#define Bsz 4
#define Lsz 1024
#define Dsz 512
#define Hsz 8
#define DKsz 64

// ---------------- scratch (static device globals; no allocation) ----------------
__device__ __nv_bfloat16 g_Qin[Bsz*Lsz*Dsz];   // query input, bf16
__device__ __nv_bfloat16 g_Kin[Bsz*Lsz*Dsz];   // key input, bf16
__device__ __nv_bfloat16 g_Wtb[4*Dsz*Dsz];     // transposed bf16 weights (wq,wk,mpq,mpk)
__device__ float g_W[2*Dsz*Dsz];               // tf32-prerounded weights (wv, dense)
__device__ __nv_bfloat16 g_Qbf[Bsz*Lsz*Dsz];   // projected q, bf16
__device__ __nv_bfloat16 g_Kbf[Bsz*Lsz*Dsz];   // projected k, bf16
__device__ __nv_bfloat16 g_QPb[Bsz*Lsz*Dsz];   // mask-perturb q proj, bf16
__device__ __nv_bfloat16 g_KPb[Bsz*Lsz*Dsz];   // mask-perturb k proj, bf16
__device__ float g_V[Bsz*Lsz*Dsz];             // tf32-prerounded
__device__ __nv_bfloat16 g_Vtb[Bsz*Hsz*DKsz*Lsz];  // V transposed [b,h,d,k], bf16
__device__ float g_CS[Bsz*Hsz*DKsz];           // colsum of V, fp32
__device__ __nv_bfloat16 g_Fb[Bsz*Lsz*Lsz];    // f = g + (1-g)exp(1-m), bf16 (head-indep)
__device__ float g_G[Bsz*Lsz];
__device__ __nv_bfloat16 g_Sb[(size_t)Bsz*Hsz*Lsz*Lsz];   // exp(scores), bf16
__device__ float g_Z[Bsz*Hsz*Lsz];
__device__ float g_CTX[Bsz*Lsz*Dsz];           // tf32-prerounded

// ---------------- helpers ----------------
__device__ __forceinline__ unsigned f2tf(float f) {
    unsigned u;
    asm("cvt.rna.tf32.f32 %0, %1;" : "=r"(u) : "f"(f));
    return u;
}
__device__ __forceinline__ float tf32r(float f) { return __uint_as_float(f2tf(f)); }

__device__ __forceinline__ unsigned packbf2(float lo, float hi) {
    unsigned r;
    asm("cvt.rn.bf16x2.f32 %0, %1, %2;" : "=r"(r) : "f"(hi), "f"(lo));
    return r;
}
__device__ __forceinline__ __nv_bfloat162 u2h2(unsigned u) {
    return *reinterpret_cast<__nv_bfloat162*>(&u);
}
__device__ __forceinline__ unsigned h22u(__nv_bfloat162 v) {
    return *reinterpret_cast<unsigned*>(&v);
}

__device__ __forceinline__ void mma_tf32(float c[4], const unsigned a[4], const unsigned b[2]) {
    asm volatile(
        "mma.sync.aligned.m16n8k8.row.col.f32.tf32.tf32.f32 "
        "{%0,%1,%2,%3}, {%4,%5,%6,%7}, {%8,%9}, {%0,%1,%2,%3};"
        : "+f"(c[0]), "+f"(c[1]), "+f"(c[2]), "+f"(c[3])
        : "r"(a[0]), "r"(a[1]), "r"(a[2]), "r"(a[3]), "r"(b[0]), "r"(b[1]));
}

__device__ __forceinline__ void mma_bf16(float c[4], const unsigned a[4], const unsigned b[2]) {
    asm volatile(
        "mma.sync.aligned.m16n8k16.row.col.f32.bf16.bf16.f32 "
        "{%0,%1,%2,%3}, {%4,%5,%6,%7}, {%8,%9}, {%0,%1,%2,%3};"
        : "+f"(c[0]), "+f"(c[1]), "+f"(c[2]), "+f"(c[3])
        : "r"(a[0]), "r"(a[1]), "r"(a[2]), "r"(a[3]), "r"(b[0]), "r"(b[1]));
}

__device__ __forceinline__ void cp_async16(void* smem, const void* gmem) {
    unsigned saddr = (unsigned)__cvta_generic_to_shared(smem);
    asm volatile("cp.async.cg.shared.global [%0], [%1], 16;" :: "r"(saddr), "l"(gmem));
}
__device__ __forceinline__ void cp_commit() { asm volatile("cp.async.commit_group;"); }
template<int N>
__device__ __forceinline__ void cp_wait() { asm volatile("cp.async.wait_group %0;" :: "n"(N)); }

// ---------------- tf32 GEMM core, 4-stage pipeline (V proj + dense) ----------------
template<int BM, int BN, bool BT, int MT, int NT, bool ACVT, bool BCVT>
__device__ __forceinline__ void gemm_core(
    const float* __restrict__ A, int lda,
    const float* __restrict__ B, int ldb,
    int K, float (&acc)[MT][NT][4])
{
    constexpr int BK = 16;
    constexpr int APITCH = BK + 4;
    constexpr int BPITCH = BT ? (BK + 4) : (BN + 8);
    constexpr int BROWS  = BT ? BN : BK;

    extern __shared__ float dynsm[];
    float* As = dynsm;
    float* Bs = dynsm + 4 * BM * APITCH;

    const int tid = threadIdx.x;
    const int lane = tid & 31;
    const int wid = tid >> 5;
    const int wm0 = (wid & 3) * (BM / 4);
    const int wn0 = (wid >> 2) * (BN / 2);

    constexpr int ALD = (BM * BK / 4) / 256;
    constexpr int BLD = (BT ? (BN * BK / 4) : (BK * BN / 4)) / 256;

    auto prefetch = [&](int k0, int s) {
        float* Asl = As + s * BM * APITCH;
        float* Bsl = Bs + s * BROWS * BPITCH;
        #pragma unroll
        for (int i = 0; i < ALD; i++) {
            int idx = tid + i * 256;
            int row = idx >> 2, kq = idx & 3;
            cp_async16(&Asl[row * APITCH + kq * 4], A + (size_t)row * lda + k0 + kq * 4);
        }
        #pragma unroll
        for (int i = 0; i < BLD; i++) {
            int idx = tid + i * 256;
            if constexpr (BT) {
                int row = idx >> 2, kq = idx & 3;
                cp_async16(&Bsl[row * BPITCH + kq * 4], B + (size_t)row * ldb + k0 + kq * 4);
            } else {
                int k = idx / (BN / 4), nq = idx % (BN / 4);
                cp_async16(&Bsl[k * BPITCH + nq * 4], B + (size_t)(k0 + k) * ldb + nq * 4);
            }
        }
        cp_commit();
    };

    const int nIter = K / BK;
    prefetch(0, 0);
    if (nIter > 1) prefetch(BK, 1);

    for (int it = 0; it < nIter; it++) {
        if (it + 2 < nIter) { prefetch((it + 2) * BK, (it + 2) & 3); cp_wait<2>(); }
        else if (it + 1 < nIter) { cp_wait<1>(); }
        else { cp_wait<0>(); }
        __syncthreads();

        const int cur = it & 3;
        const float* Asl = As + cur * BM * APITCH;
        const float* Bsl = Bs + cur * BROWS * BPITCH;
        const unsigned* Aslu = (const unsigned*)Asl;
        const unsigned* Bslu = (const unsigned*)Bsl;

        #pragma unroll
        for (int ks = 0; ks < 2; ks++) {
            unsigned af[MT][4];
            unsigned bf[NT][2];
            const int kk = ks * 8 + (lane & 3);
            #pragma unroll
            for (int mt = 0; mt < MT; mt++) {
                int row = wm0 + mt * 16 + (lane >> 2);
                if constexpr (ACVT) {
                    af[mt][0] = f2tf(Asl[row * APITCH + kk]);
                    af[mt][1] = f2tf(Asl[(row + 8) * APITCH + kk]);
                    af[mt][2] = f2tf(Asl[row * APITCH + kk + 4]);
                    af[mt][3] = f2tf(Asl[(row + 8) * APITCH + kk + 4]);
                } else {
                    af[mt][0] = Aslu[row * APITCH + kk];
                    af[mt][1] = Aslu[(row + 8) * APITCH + kk];
                    af[mt][2] = Aslu[row * APITCH + kk + 4];
                    af[mt][3] = Aslu[(row + 8) * APITCH + kk + 4];
                }
            }
            #pragma unroll
            for (int nt = 0; nt < NT; nt++) {
                int n = wn0 + nt * 8 + (lane >> 2);
                if constexpr (BT) {
                    if constexpr (BCVT) {
                        bf[nt][0] = f2tf(Bsl[n * BPITCH + kk]);
                        bf[nt][1] = f2tf(Bsl[n * BPITCH + kk + 4]);
                    } else {
                        bf[nt][0] = Bslu[n * BPITCH + kk];
                        bf[nt][1] = Bslu[n * BPITCH + kk + 4];
                    }
                } else {
                    if constexpr (BCVT) {
                        bf[nt][0] = f2tf(Bsl[kk * BPITCH + n]);
                        bf[nt][1] = f2tf(Bsl[(kk + 4) * BPITCH + n]);
                    } else {
                        bf[nt][0] = Bslu[kk * BPITCH + n];
                        bf[nt][1] = Bslu[(kk + 4) * BPITCH + n];
                    }
                }
            }
            #pragma unroll
            for (int mt = 0; mt < MT; mt++)
                #pragma unroll
                for (int nt = 0; nt < NT; nt++)
                    mma_tf32(acc[mt][nt], af[mt], bf[nt]);
        }
    }
}

// smem byte sizes
#define PROJ_SMEM  ((4*128*20 + 4*16*136) * 4)   // 75776 (tf32 path)
#define NTG_SMEM   (4*128*40*2 * 2)              // 81920 (bf16 4-stage NT)
#define CTX_S_BYTES   (4 * 128 * 24 * 2)
#define CTX_E_BYTES   (4 * 128 * 24 * 2)
#define CTX_V_BYTES   (4 * 64 * 24 * 2)
#define CTXF_SMEM  (CTX_S_BYTES + CTX_E_BYTES + CTX_V_BYTES)  // 61440

// ---------------- unified prep: preround(2) + wtrans(4) + incvt(2) ----------------
struct PrepArgs {
    const float* pr[2];
    const float* wt[4];
    const float* q;
    const float* k;
};

__global__ void __launch_bounds__(256) prep_kernel(PrepArgs a)
{
    __shared__ float tile[32][33];
    const int bid = blockIdx.x;
    const int tid = threadIdx.x;

    if (bid < 512) {
        const int z = bid >> 8;
        const int idx = (bid & 255) * 256 + tid;
        float4 v = ((const float4*)a.pr[z])[idx];
        ((float4*)(g_W + z * Dsz * Dsz))[idx] =
            make_float4(tf32r(v.x), tf32r(v.y), tf32r(v.z), tf32r(v.w));
    } else if (bid < 1536) {
        const int t = bid - 512;
        const int z = t >> 8;
        const int c0 = (t & 15) * 32, r0 = ((t >> 4) & 15) * 32;
        const float* W = a.wt[z];
        const int tx = tid & 31, ty = tid >> 5;
        #pragma unroll
        for (int i = 0; i < 4; i++)
            tile[ty + i * 8][tx] = W[(size_t)(r0 + ty + i * 8) * Dsz + c0 + tx];
        __syncthreads();
        __nv_bfloat16* Wt = g_Wtb + (size_t)z * Dsz * Dsz;
        #pragma unroll
        for (int i = 0; i < 4; i++)
            Wt[(size_t)(c0 + ty + i * 8) * Dsz + r0 + tx] =
                __float2bfloat16(tile[tx][ty + i * 8]);
    } else {
        const int t = bid - 1536;
        const int y = t >> 11;
        const float* src = y ? a.k : a.q;
        __nv_bfloat16* dst = y ? g_Kin : g_Qin;
        const int idx = (t & 2047) * 256 + tid;
        float4 v = ((const float4*)src)[idx];
        ((uint2*)dst)[idx] = make_uint2(packbf2(v.x, v.y), packbf2(v.z, v.w));
    }
}

// ---------------- combined projections: 4x bf16 NT + 1x tf32 NN (V) + gate (z=5) ----------------
struct ProjAll {
    const __nv_bfloat16* A[4];
    const __nv_bfloat16* Wt[4];
    const float* bias[4];
    __nv_bfloat16* C[4];
    const float* vA; const float* vW; const float* vbias; float* vC;
    const float* q; const float* gw; const float* gb;
};

__global__ void __launch_bounds__(256, 2) projall_kernel(ProjAll a)
{
    const int zz = blockIdx.z;
    const int tid = threadIdx.x;
    const int lane = tid & 31, wid = tid >> 5;
    const int fcol = lane & 3;
    extern __shared__ float dynsm[];

    if (zz < 4) {
        const __nv_bfloat16* Ab = a.A[zz] + ((size_t)blockIdx.y * 128) * Dsz;
        const __nv_bfloat16* Bb = a.Wt[zz] + ((size_t)blockIdx.x * 128) * Dsz;

        __nv_bfloat16* As = (__nv_bfloat16*)dynsm;
        __nv_bfloat16* Bs = As + 4 * 128 * 40;

        auto pre = [&](int it, int s) {
            const int k0 = it * 32;
            __nv_bfloat16* Al = As + s * 128 * 40;
            __nv_bfloat16* Bl = Bs + s * 128 * 40;
            #pragma unroll
            for (int i = 0; i < 2; i++) {
                int idx = tid + i * 256;
                int row = idx >> 2, ch = idx & 3;
                cp_async16(&Al[row * 40 + ch * 8], Ab + (size_t)row * Dsz + k0 + ch * 8);
                cp_async16(&Bl[row * 40 + ch * 8], Bb + (size_t)row * Dsz + k0 + ch * 8);
            }
            cp_commit();
        };

        const int wm0 = (wid & 3) * 32;
        const int wn0 = (wid >> 2) * 64;
        const int frow = lane >> 2;
        float acc[2][8][4] = {};

        const int nIter = Dsz / 32;
        pre(0, 0);
        pre(1, 1);

        for (int it = 0; it < nIter; it++) {
            if (it + 2 < nIter) { pre(it + 2, (it + 2) & 3); cp_wait<2>(); }
            else if (it + 1 < nIter) { cp_wait<1>(); }
            else { cp_wait<0>(); }
            __syncthreads();

            const int cur = it & 3;
            const unsigned* Aw = (const unsigned*)(As + cur * 128 * 40);
            const unsigned* Bw = (const unsigned*)(Bs + cur * 128 * 40);

            #pragma unroll
            for (int ks = 0; ks < 2; ks++) {
                const int kw = ks * 8 + fcol;
                unsigned af[2][4];
                #pragma unroll
                for (int mt = 0; mt < 2; mt++) {
                    int row = wm0 + mt * 16 + frow;
                    af[mt][0] = Aw[row * 20 + kw];
                    af[mt][1] = Aw[(row + 8) * 20 + kw];
                    af[mt][2] = Aw[row * 20 + kw + 4];
                    af[mt][3] = Aw[(row + 8) * 20 + kw + 4];
                }
                #pragma unroll
                for (int nt = 0; nt < 8; nt++) {
                    int n = wn0 + nt * 8 + frow;
                    unsigned bf[2] = { Bw[n * 20 + kw], Bw[n * 20 + kw + 4] };
                    #pragma unroll
                    for (int mt = 0; mt < 2; mt++)
                        mma_bf16(acc[mt][nt], af[mt], bf);
                }
            }
        }

        const float* bias = a.bias[zz];
        __nv_bfloat16* C = a.C[zz];
        int rowBase = blockIdx.y * 128 + wm0 + frow;
        int colBase = blockIdx.x * 128 + wn0 + 2 * fcol;
        #pragma unroll
        for (int mt = 0; mt < 2; mt++)
            #pragma unroll
            for (int nt = 0; nt < 8; nt++) {
                int row = rowBase + mt * 16;
                int col = colBase + nt * 8;
                float b0 = bias[col], b1 = bias[col + 1];
                *(__nv_bfloat162*)&C[(size_t)row * Dsz + col] =
                    __floats2bfloat162_rn(acc[mt][nt][0] + b0, acc[mt][nt][1] + b1);
                *(__nv_bfloat162*)&C[(size_t)(row + 8) * Dsz + col] =
                    __floats2bfloat162_rn(acc[mt][nt][2] + b0, acc[mt][nt][3] + b1);
            }
    } else if (zz == 4) {
        float acc[2][8][4] = {};
        const float* Ab = a.vA + (size_t)blockIdx.y * 128 * Dsz;
        const float* Bb = a.vW + blockIdx.x * 128;
        gemm_core<128, 128, false, 2, 8, true, false>(Ab, Dsz, Bb, Dsz, Dsz, acc);

        const float* bias = a.vbias;
        float* C = a.vC;
        int rowBase = blockIdx.y * 128 + (wid & 3) * 32 + (lane >> 2);
        int colBase = blockIdx.x * 128 + (wid >> 2) * 64 + 2 * fcol;
        #pragma unroll
        for (int mt = 0; mt < 2; mt++)
            #pragma unroll
            for (int nt = 0; nt < 8; nt++) {
                int row = rowBase + mt * 16;
                int col = colBase + nt * 8;
                float b0 = bias[col], b1 = bias[col + 1];
                *(float2*)&C[(size_t)row * Dsz + col] =
                    make_float2(tf32r(acc[mt][nt][0] + b0), tf32r(acc[mt][nt][1] + b1));
                *(float2*)&C[(size_t)(row + 8) * Dsz + col] =
                    make_float2(tf32r(acc[mt][nt][2] + b0), tf32r(acc[mt][nt][3] + b1));
            }
    } else {
        const int bid = blockIdx.y * 4 + blockIdx.x;
        const int gidx = bid * 256 + tid;
        g_Z[gidx] = 0.f;
        if (gidx < Bsz * Hsz * DKsz) g_CS[gidx] = 0.f;

        const float4* gw4 = (const float4*)a.gw;
        #pragma unroll
        for (int p = 0; p < 4; p++) {
            const int row = bid * 32 + p * 8 + wid;
            const float4* r4 = (const float4*)(a.q + (size_t)row * Dsz);
            float s = 0.f;
            #pragma unroll
            for (int i = 0; i < 4; i++) {
                float4 v = r4[lane + i * 32];
                float4 w = gw4[lane + i * 32];
                s += v.x * w.x + v.y * w.y + v.z * w.z + v.w * w.w;
            }
            #pragma unroll
            for (int o = 16; o; o >>= 1) s += __shfl_xor_sync(0xffffffffu, s, o);
            if (lane == 0)
                g_G[row] = 1.0f / (1.0f + __expf(-(s + a.gb[0])));
        }
    }
}

// ---------------- dense: tf32 NN, plain fp32 out ----------------
__global__ void __launch_bounds__(256, 2) dense_gemm_kernel(
    const float* __restrict__ A, const float* __restrict__ W,
    const float* __restrict__ bias, float* __restrict__ C)
{
    float acc[2][8][4] = {};
    const float* Ab = A + (size_t)blockIdx.y * 128 * Dsz;
    const float* Bb = W + blockIdx.x * 128;
    gemm_core<128, 128, false, 2, 8, false, false>(Ab, Dsz, Bb, Dsz, Dsz, acc);

    int lane = threadIdx.x & 31, wid = threadIdx.x >> 5;
    int rowBase = blockIdx.y * 128 + (wid & 3) * 32 + (lane >> 2);
    int colBase = blockIdx.x * 128 + (wid >> 2) * 64 + 2 * (lane & 3);
    #pragma unroll
    for (int mt = 0; mt < 2; mt++)
        #pragma unroll
        for (int nt = 0; nt < 8; nt++) {
            int row = rowBase + mt * 16;
            int col = colBase + nt * 8;
            float b0 = bias[col], b1 = bias[col + 1];
            *(float2*)&C[(size_t)row * Dsz + col] =
                make_float2(acc[mt][nt][0] + b0, acc[mt][nt][1] + b1);
            *(float2*)&C[(size_t)(row + 8) * Dsz + col] =
                make_float2(acc[mt][nt][2] + b0, acc[mt][nt][3] + b1);
        }
}

// ---------------- merged m + score + vprep launch ----------------
// m-path epilogue writes F = g + (1-g)exp(1-m) (head-independent calibration factor).
__global__ void __launch_bounds__(256, 2) ms_gemm_kernel(float* __restrict__ m_out)
{
    const int zz = blockIdx.z;
    const int tid = threadIdx.x;
    int lane = tid & 31, wid = tid >> 5;
    int fcol = lane & 3;
    extern __shared__ float dynsm[];

    if (zz < Bsz) {
        const float SCALE = 0.04419417382415922f; // 1/sqrt(512)
        const int zb = zz;
        const __nv_bfloat16* Ab = g_QPb + ((size_t)zb * Lsz + blockIdx.y * 128) * Dsz;
        const __nv_bfloat16* Bb = g_KPb + ((size_t)zb * Lsz + blockIdx.x * 128) * Dsz;

        __nv_bfloat16* As = (__nv_bfloat16*)dynsm;
        __nv_bfloat16* Bs = As + 4 * 128 * 40;

        auto pre = [&](int it, int s) {
            const int k0 = it * 32;
            __nv_bfloat16* Al = As + s * 128 * 40;
            __nv_bfloat16* Bl = Bs + s * 128 * 40;
            #pragma unroll
            for (int i = 0; i < 2; i++) {
                int idx = tid + i * 256;
                int row = idx >> 2, ch = idx & 3;
                cp_async16(&Al[row * 40 + ch * 8], Ab + (size_t)row * Dsz + k0 + ch * 8);
                cp_async16(&Bl[row * 40 + ch * 8], Bb + (size_t)row * Dsz + k0 + ch * 8);
            }
            cp_commit();
        };

        const int wm0 = (wid & 3) * 32;
        const int wn0 = (wid >> 2) * 64;
        const int frow = lane >> 2;
        float acc[2][8][4] = {};

        const int nIter = Dsz / 32;
        pre(0, 0);
        pre(1, 1);

        for (int it = 0; it < nIter; it++) {
            if (it + 2 < nIter) { pre(it + 2, (it + 2) & 3); cp_wait<2>(); }
            else if (it + 1 < nIter) { cp_wait<1>(); }
            else { cp_wait<0>(); }
            __syncthreads();

            const int cur = it & 3;
            const unsigned* Aw = (const unsigned*)(As + cur * 128 * 40);
            const unsigned* Bw = (const unsigned*)(Bs + cur * 128 * 40);

            #pragma unroll
            for (int ks = 0; ks < 2; ks++) {
                const int kw = ks * 8 + fcol;
                unsigned af[2][4];
                #pragma unroll
                for (int mt = 0; mt < 2; mt++) {
                    int row = wm0 + mt * 16 + frow;
                    af[mt][0] = Aw[row * 20 + kw];
                    af[mt][1] = Aw[(row + 8) * 20 + kw];
                    af[mt][2] = Aw[row * 20 + kw + 4];
                    af[mt][3] = Aw[(row + 8) * 20 + kw + 4];
                }
                #pragma unroll
                for (int nt = 0; nt < 8; nt++) {
                    int n = wn0 + nt * 8 + frow;
                    unsigned bf[2] = { Bw[n * 20 + kw], Bw[n * 20 + kw + 4] };
                    #pragma unroll
                    for (int mt = 0; mt < 2; mt++)
                        mma_bf16(acc[mt][nt], af[mt], bf);
                }
            }
        }

        float* Mo = m_out + (size_t)zb * Lsz * Lsz;
        __nv_bfloat16* Fo = g_Fb + (size_t)zb * Lsz * Lsz;
        int rowBase = blockIdx.y * 128 + wm0 + frow;
        int colBase = blockIdx.x * 128 + wn0 + 2 * fcol;
        #pragma unroll
        for (int mt = 0; mt < 2; mt++)
            #pragma unroll
            for (int nt = 0; nt < 8; nt++) {
                int row = rowBase + mt * 16;
                int col = colBase + nt * 8;
                #pragma unroll
                for (int h = 0; h < 2; h++) {
                    int r = row + h * 8;
                    float g = g_G[zb * Lsz + r];
                    float s0 = 1.0f / (1.0f + __expf(-acc[mt][nt][2*h] * SCALE));
                    float s1 = 1.0f / (1.0f + __expf(-acc[mt][nt][2*h+1] * SCALE));
                    *(float2*)&Mo[(size_t)r * Lsz + col] = make_float2(s0, s1);
                    float f0 = fmaf(1.0f - g, __expf(1.0f - s0), g);
                    float f1 = fmaf(1.0f - g, __expf(1.0f - s1), g);
                    *(__nv_bfloat162*)&Fo[(size_t)r * Lsz + col] =
                        __floats2bfloat162_rn(f0, f1);
                }
            }
    } else if (zz < Bsz + Bsz * Hsz) {
        const float SCALE = 0.125f;
        const int z = zz - Bsz;
        const int b = z >> 3, h = z & 7;
        const __nv_bfloat16* Ab = g_Qbf + ((size_t)b * Lsz + blockIdx.y * 128) * Dsz + h * DKsz;
        const __nv_bfloat16* Bb = g_Kbf + ((size_t)b * Lsz + blockIdx.x * 128) * Dsz + h * DKsz;

        __nv_bfloat16* Qs = (__nv_bfloat16*)dynsm;
        __nv_bfloat16* Ks = Qs + 128 * 88;
        const unsigned* Qw = (const unsigned*)Qs;
        const unsigned* Kw = (const unsigned*)Ks;

        #pragma unroll
        for (int i = 0; i < 4; i++) {
            int idx = tid + i * 256;
            int row = idx >> 3, ch = idx & 7;
            cp_async16(&Qs[row * 88 + ch * 8], Ab + (size_t)row * Dsz + ch * 8);
        }
        #pragma unroll
        for (int i = 0; i < 4; i++) {
            int idx = tid + i * 256;
            int row = idx >> 3, ch = idx & 7;
            cp_async16(&Ks[row * 88 + ch * 8], Bb + (size_t)row * Dsz + ch * 8);
        }
        cp_commit();
        cp_wait<0>();
        __syncthreads();

        const int wm0 = (wid & 3) * 32;
        const int wn0 = (wid >> 2) * 64;
        const int frow = lane >> 2;
        float acc[2][8][4] = {};

        #pragma unroll
        for (int ks = 0; ks < 4; ks++) {
            const int kw = ks * 8 + fcol;
            unsigned af[2][4];
            #pragma unroll
            for (int mt = 0; mt < 2; mt++) {
                int row = wm0 + mt * 16 + frow;
                af[mt][0] = Qw[row * 44 + kw];
                af[mt][1] = Qw[(row + 8) * 44 + kw];
                af[mt][2] = Qw[row * 44 + kw + 4];
                af[mt][3] = Qw[(row + 8) * 44 + kw + 4];
            }
            #pragma unroll
            for (int nt = 0; nt < 8; nt++) {
                int n = wn0 + nt * 8 + frow;
                unsigned bf[2] = { Kw[n * 44 + kw], Kw[n * 44 + kw + 4] };
                #pragma unroll
                for (int mt = 0; mt < 2; mt++)
                    mma_bf16(acc[mt][nt], af[mt], bf);
            }
        }

        __nv_bfloat16* Cp = g_Sb + (size_t)z * Lsz * Lsz;
        int rowBase = blockIdx.y * 128 + wm0 + frow;
        int colBase = blockIdx.x * 128 + wn0 + 2 * fcol;

        float rs[2][2] = {};
        #pragma unroll
        for (int mt = 0; mt < 2; mt++)
            #pragma unroll
            for (int nt = 0; nt < 8; nt++) {
                int row = rowBase + mt * 16;
                int col = colBase + nt * 8;
                float p0 = __expf(acc[mt][nt][0] * SCALE);
                float p1 = __expf(acc[mt][nt][1] * SCALE);
                float p2 = __expf(acc[mt][nt][2] * SCALE);
                float p3 = __expf(acc[mt][nt][3] * SCALE);
                *(__nv_bfloat162*)&Cp[(size_t)row * Lsz + col] =
                    __floats2bfloat162_rn(p0, p1);
                *(__nv_bfloat162*)&Cp[(size_t)(row + 8) * Lsz + col] =
                    __floats2bfloat162_rn(p2, p3);
                rs[mt][0] += p0 + p1;
                rs[mt][1] += p2 + p3;
            }

        #pragma unroll
        for (int mt = 0; mt < 2; mt++)
            #pragma unroll
            for (int hh = 0; hh < 2; hh++) {
                float v = rs[mt][hh];
                v += __shfl_xor_sync(0xffffffffu, v, 1);
                v += __shfl_xor_sync(0xffffffffu, v, 2);
                if (fcol == 0)
                    atomicAdd(&g_Z[(size_t)z * Lsz + rowBase + mt * 16 + hh * 8], v);
            }
    } else {
        __nv_bfloat16 (*sm)[72] = (__nv_bfloat16(*)[72])dynsm;
        const int b = zz - (Bsz + Bsz * Hsz);
        const int h = blockIdx.y, kt = blockIdx.x;
        const int k0 = kt * 128;

        const int d = tid & 63, rg = tid >> 6;
        float psum = 0.f;
        #pragma unroll
        for (int j = 0; j < 32; j++) {
            int row = rg + 4 * j;
            float v = g_V[((size_t)(b * Lsz + k0 + row)) * Dsz + h * DKsz + d];
            psum += v;
            sm[row][d] = __float2bfloat16(v);
        }
        atomicAdd(&g_CS[(b * Hsz + h) * DKsz + d], psum);
        __syncthreads();

        const int d2 = tid >> 2, c = tid & 3;
        __nv_bfloat16* dst = g_Vtb + ((size_t)((b * Hsz + h) * DKsz + d2)) * Lsz + k0 + c * 32;
        #pragma unroll
        for (int q = 0; q < 4; q++) {
            __nv_bfloat16 tmp[8];
            #pragma unroll
            for (int e = 0; e < 8; e++) tmp[e] = sm[c * 32 + q * 8 + e][d2];
            *(uint4*)(dst + q * 8) = *(uint4*)tmp;
        }
    }
}

// ---------------- fused calibrate + ctx GEMM: bf16x2 SIMD transform ----------------
// x = s * f * invZ (HMUL2 x2), y = x + x^2/2 (HMUL2+HFMA2); y bits feed MMA directly.
__global__ void __launch_bounds__(256, 2) ctx_fused_kernel()
{
    extern __shared__ char smc[];
    __nv_bfloat16* Ss = (__nv_bfloat16*)smc;
    __nv_bfloat16* Fs = (__nv_bfloat16*)(smc + CTX_S_BYTES);
    __nv_bfloat16* Vs = (__nv_bfloat16*)(smc + CTX_S_BYTES + CTX_E_BYTES);

    const int tid = threadIdx.x;
    const int lane = tid & 31;
    const int wid = tid >> 5;
    const int z = blockIdx.z;
    const int b = z >> 3, h = z & 7;
    const int q0 = blockIdx.y * 128;

    const __nv_bfloat16* Sg = g_Sb + (size_t)z * Lsz * Lsz + (size_t)q0 * Lsz;
    const __nv_bfloat16* Fg = g_Fb + (size_t)b * Lsz * Lsz + (size_t)q0 * Lsz;
    const __nv_bfloat16* Vtg = g_Vtb + (size_t)z * DKsz * Lsz;

    const int wm = wid * 16;
    const int frow = lane >> 2, fcol = lane & 3;
    const int r0 = wm + frow, r1 = r0 + 8;

    const float iz0 = 1.0f / g_Z[(size_t)z * Lsz + q0 + r0];
    const float iz1 = 1.0f / g_Z[(size_t)z * Lsz + q0 + r1];
    const __nv_bfloat162 iz0h = __float2bfloat162_rn(iz0);
    const __nv_bfloat162 iz1h = __float2bfloat162_rn(iz1);
    const __nv_bfloat162 half2 = __float2bfloat162_rn(0.5f);
    float z2a = 0.f, z2b = 0.f;

    auto prefetch = [&](int it, int s) {
        const int k0 = it * 16;
        __nv_bfloat16* Sl = Ss + s * 128 * 24;
        __nv_bfloat16* Fl = Fs + s * 128 * 24;
        __nv_bfloat16* Vl = Vs + s * 64 * 24;
        {
            int row = tid >> 1, ch = tid & 1;
            cp_async16(&Sl[row * 24 + ch * 8], Sg + (size_t)row * Lsz + k0 + ch * 8);
            cp_async16(&Fl[row * 24 + ch * 8], Fg + (size_t)row * Lsz + k0 + ch * 8);
        }
        if (tid < 128) {
            int d = tid >> 1, half = tid & 1;
            cp_async16(&Vl[d * 24 + half * 8], Vtg + (size_t)d * Lsz + k0 + half * 8);
        }
        cp_commit();
    };

    float acc[8][4] = {};
    const int nIter = Lsz / 16;
    prefetch(0, 0);
    prefetch(1, 1);

    for (int it = 0; it < nIter; it++) {
        if (it + 2 < nIter) { prefetch(it + 2, (it + 2) & 3); cp_wait<2>(); }
        else if (it + 1 < nIter) { cp_wait<1>(); }
        else { cp_wait<0>(); }
        __syncthreads();

        const int cur = it & 3;
        const unsigned* Sw = (const unsigned*)(Ss + cur * 128 * 24);
        const unsigned* Fw = (const unsigned*)(Fs + cur * 128 * 24);
        const unsigned* Vw = (const unsigned*)(Vs + cur * 64 * 24);

        // bf16x2 transform: 4 registers = exact MMA A-fragment layout
        __nv_bfloat162 x0 = __hmul2(__hmul2(u2h2(Sw[r0 * 12 + fcol]),     u2h2(Fw[r0 * 12 + fcol])),     iz0h);
        __nv_bfloat162 x1 = __hmul2(__hmul2(u2h2(Sw[r1 * 12 + fcol]),     u2h2(Fw[r1 * 12 + fcol])),     iz1h);
        __nv_bfloat162 x2 = __hmul2(__hmul2(u2h2(Sw[r0 * 12 + fcol + 4]), u2h2(Fw[r0 * 12 + fcol + 4])), iz0h);
        __nv_bfloat162 x3 = __hmul2(__hmul2(u2h2(Sw[r1 * 12 + fcol + 4]), u2h2(Fw[r1 * 12 + fcol + 4])), iz1h);

        __nv_bfloat162 y0 = __hfma2(__hmul2(x0, half2), x0, x0);
        __nv_bfloat162 y1 = __hfma2(__hmul2(x1, half2), x1, x1);
        __nv_bfloat162 y2 = __hfma2(__hmul2(x2, half2), x2, x2);
        __nv_bfloat162 y3 = __hfma2(__hmul2(x3, half2), x3, x3);

        float2 t0 = __bfloat1622float2(y0);
        float2 t1 = __bfloat1622float2(y1);
        float2 t2 = __bfloat1622float2(y2);
        float2 t3 = __bfloat1622float2(y3);
        z2a += (t0.x + t0.y) + (t2.x + t2.y);
        z2b += (t1.x + t1.y) + (t3.x + t3.y);

        unsigned af[4] = { h22u(y0), h22u(y1), h22u(y2), h22u(y3) };

        #pragma unroll
        for (int nt = 0; nt < 8; nt++) {
            const int n = nt * 8 + frow;
            unsigned bf[2] = { Vw[n * 12 + fcol], Vw[n * 12 + fcol + 4] };
            mma_bf16(acc[nt], af, bf);
        }
    }

    z2a += __shfl_xor_sync(0xffffffffu, z2a, 1);
    z2a += __shfl_xor_sync(0xffffffffu, z2a, 2);
    z2b += __shfl_xor_sync(0xffffffffu, z2b, 1);
    z2b += __shfl_xor_sync(0xffffffffu, z2b, 2);
    const float iza = 1.0f / (1024.0f + z2a);
    const float izb = 1.0f / (1024.0f + z2b);

    float* Cp = g_CTX + (size_t)b * Lsz * Dsz + (size_t)q0 * Dsz + h * DKsz;
    const float* CSp = g_CS + z * DKsz;
    #pragma unroll
    for (int nt = 0; nt < 8; nt++) {
        const int col = nt * 8 + 2 * fcol;
        float cs0 = CSp[col], cs1 = CSp[col + 1];
        *(float2*)&Cp[(size_t)r0 * Dsz + col] =
            make_float2(tf32r((cs0 + acc[nt][0]) * iza), tf32r((cs1 + acc[nt][1]) * iza));
        *(float2*)&Cp[(size_t)r1 * Dsz + col] =
            make_float2(tf32r((cs0 + acc[nt][2]) * izb), tf32r((cs1 + acc[nt][3]) * izb));
    }
}

// ---------------- launch ----------------
extern "C" void kernel_launch(void* const* d_in, const int* in_sizes, int n_in,
                              void* d_out, int out_size)
{
    const float* query   = (const float*)d_in[0];
    const float* key     = (const float*)d_in[1];
    const float* value   = (const float*)d_in[2];
    const float* wq_w    = (const float*)d_in[3];
    const float* wq_b    = (const float*)d_in[4];
    const float* wk_w    = (const float*)d_in[5];
    const float* wk_b    = (const float*)d_in[6];
    const float* wv_w    = (const float*)d_in[7];
    const float* wv_b    = (const float*)d_in[8];
    const float* dense_w = (const float*)d_in[9];
    const float* dense_b = (const float*)d_in[10];
    const float* gate_w  = (const float*)d_in[11];
    const float* gate_b  = (const float*)d_in[12];
    const float* mp_wq_w = (const float*)d_in[13];
    const float* mp_wq_b = (const float*)d_in[14];
    const float* mp_wk_w = (const float*)d_in[15];
    const float* mp_wk_b = (const float*)d_in[16];

    float* out   = (float*)d_out;
    float* m_out = out + (size_t)Bsz * Lsz * Dsz;

    void *pQin, *pKin, *pWtb, *pQbf, *pKbf, *pQPb, *pKPb;
    float *pV, *pCTX, *pW;
    cudaGetSymbolAddress(&pQin, g_Qin);
    cudaGetSymbolAddress(&pKin, g_Kin);
    cudaGetSymbolAddress(&pWtb, g_Wtb);
    cudaGetSymbolAddress(&pQbf, g_Qbf);
    cudaGetSymbolAddress(&pKbf, g_Kbf);
    cudaGetSymbolAddress(&pQPb, g_QPb);
    cudaGetSymbolAddress(&pKPb, g_KPb);
    cudaGetSymbolAddress((void**)&pV,   g_V);
    cudaGetSymbolAddress((void**)&pCTX, g_CTX);
    cudaGetSymbolAddress((void**)&pW,   g_W);

    static int attr_set = 0;
    if (!attr_set) {
        cudaFuncSetAttribute(projall_kernel,
                             cudaFuncAttributeMaxDynamicSharedMemorySize, NTG_SMEM);
        cudaFuncSetAttribute(dense_gemm_kernel,
                             cudaFuncAttributeMaxDynamicSharedMemorySize, PROJ_SMEM);
        cudaFuncSetAttribute(ms_gemm_kernel,
                             cudaFuncAttributeMaxDynamicSharedMemorySize, NTG_SMEM);
        cudaFuncSetAttribute(ctx_fused_kernel,
                             cudaFuncAttributeMaxDynamicSharedMemorySize, CTXF_SMEM);
        attr_set = 1;
    }

    dim3 t256(256);

    PrepArgs prep;
    prep.pr[0] = wv_w; prep.pr[1] = dense_w;
    prep.wt[0] = wq_w; prep.wt[1] = wk_w; prep.wt[2] = mp_wq_w; prep.wt[3] = mp_wk_w;
    prep.q = query; prep.k = key;
    prep_kernel<<<5632, t256>>>(prep);

    ProjAll pa;
    pa.A[0] = (const __nv_bfloat16*)pQin; pa.Wt[0] = (const __nv_bfloat16*)pWtb + 0*Dsz*Dsz;
    pa.bias[0] = wq_b;    pa.C[0] = (__nv_bfloat16*)pQbf;
    pa.A[1] = (const __nv_bfloat16*)pKin; pa.Wt[1] = (const __nv_bfloat16*)pWtb + 1*Dsz*Dsz;
    pa.bias[1] = wk_b;    pa.C[1] = (__nv_bfloat16*)pKbf;
    pa.A[2] = (const __nv_bfloat16*)pQin; pa.Wt[2] = (const __nv_bfloat16*)pWtb + 2*Dsz*Dsz;
    pa.bias[2] = mp_wq_b; pa.C[2] = (__nv_bfloat16*)pQPb;
    pa.A[3] = (const __nv_bfloat16*)pKin; pa.Wt[3] = (const __nv_bfloat16*)pWtb + 3*Dsz*Dsz;
    pa.bias[3] = mp_wk_b; pa.C[3] = (__nv_bfloat16*)pKPb;
    pa.vA = value; pa.vW = pW + 0*Dsz*Dsz; pa.vbias = wv_b; pa.vC = pV;
    pa.q = query; pa.gw = gate_w; pa.gb = gate_b;
    projall_kernel<<<dim3(4, 32, 6), t256, NTG_SMEM>>>(pa);

    ms_gemm_kernel<<<dim3(8, 8, Bsz + Bsz * Hsz + Bsz), t256, NTG_SMEM>>>(m_out);

    ctx_fused_kernel<<<dim3(1, 8, Bsz * Hsz), t256, CTXF_SMEM>>>();

    dense_gemm_kernel<<<dim3(4, 32), t256, PROJ_SMEM>>>(pCTX, pW + 1*Dsz*Dsz, dense_b, out);
}